// round 14
// baseline (speedup 1.0000x reference)
#include <cuda_runtime.h>
#include <cstdint>

#define TT 50
#define NUSERS 4096
#define NDOCS 50
#define DD 64
#define LU 32
#define ZDIM 128
#define UB 8           // users per block
#define X1S 132        // padded x1 row

typedef unsigned long long u64;

__device__ __forceinline__ u64 pack2(float lo, float hi) {
    u64 r; asm("mov.b64 %0, {%1, %2};" : "=l"(r) : "f"(lo), "f"(hi)); return r;
}
__device__ __forceinline__ void unpack2(u64 v, float& lo, float& hi) {
    asm("mov.b64 {%0, %1}, %2;" : "=f"(lo), "=f"(hi) : "l"(v));
}
__device__ __forceinline__ u64 ffma2(u64 a, u64 b, u64 c) {
    u64 d; asm("fma.rn.f32x2 %0, %1, %2, %3;" : "=l"(d) : "l"(a), "l"(b), "l"(c)); return d;
}

// -------- dynamic smem layout (float offsets) --------
#define OFF_X1    0                        // 6600  (16B aligned: 0)
#define OFF_PSUM  (OFF_X1 + NDOCS * X1S)   // 6600
#define OFF_UPS   (OFF_PSUM + 2 * NDOCS * 33)  // 9900  (*4 = 39600, %16 == 0)
#define OFF_UE    (OFF_UPS + UB * ZDIM)    // 10924
#define OFF_T1    (OFF_UE + UB * DD)       // 11436
#define OFF_HB    (OFF_T1 + UB * LU)       // 11692 (*4 = 46768, %16 == 0)
#define OFF_PCS   (OFF_HB + UB * LU)       // 11948 (even -> float2 ok)
#define OFF_QW    (OFF_PCS + UB * 52 * 2)  // 12780
#define OFF_N2B   (OFF_QW + 32)            // 12812
#define SMEM_FLOATS (OFF_N2B + 32)         // 12844
#define SMEM_BYTES  (SMEM_FLOATS * 4)      // 51376

// -------- device scratch --------
__device__ __align__(16) float g_P[(NDOCS + 1) * ZDIM];   // [id][lane][gate]
__device__ __align__(16) float g_dpart[NDOCS * ZDIM];

__device__ __forceinline__ float sigf(float x) { return 1.0f / (1.0f + __expf(-x)); }
__device__ __forceinline__ float tanhfast(float x) { return 2.0f / (1.0f + __expf(-2.0f * x)) - 1.0f; }

// ---------------- K0: precompute P (lane-gate layout) and dpart ----------------
__global__ void precompute_kernel(const float* __restrict__ doc_embed,
                                  const float* __restrict__ lstm_Wx,
                                  const float* __restrict__ lstm_b,
                                  const float* __restrict__ doc_prop,
                                  const float* __restrict__ n1_W,
                                  const float* __restrict__ n1_b) {
    int c = threadIdx.x;
    int b = blockIdx.x;
    if (b <= NDOCS) {
        int lane = c >> 2, g = c & 3;
        int col = g * 32 + lane;
        float acc = lstm_b[col];
#pragma unroll 8
        for (int k = 0; k < DD; k++)
            acc = fmaf(doc_embed[b * DD + k], lstm_Wx[k * ZDIM + col], acc);
        g_P[b * ZDIM + c] = acc;
    } else {
        int d = b - (NDOCS + 1);
        float acc = n1_b[c];
#pragma unroll 8
        for (int k = 0; k < DD; k++)
            acc = fmaf(doc_prop[(d + 1) * DD + k], n1_W[(DD + k) * ZDIM + c], acc);
        g_dpart[d * ZDIM + c] = acc;
    }
}

// ---------------- MEGA kernel: LSTM + head + Q-net + slate, 8 users/block ----------------
__global__ __launch_bounds__(256)
void mega_kernel(const int* __restrict__ doc_ids,
                 const float* __restrict__ ctime,
                 const float* __restrict__ lstm_Wh,
                 const float* __restrict__ lstm_Wx,
                 const float* __restrict__ d1_W, const float* __restrict__ d1_b,
                 const float* __restrict__ he_W, const float* __restrict__ he_b,
                 const float* __restrict__ n1_W,
                 const float* __restrict__ n2_W, const float* __restrict__ n2_b,
                 const float* __restrict__ q_W, const float* __restrict__ q_b,
                 const float* __restrict__ doc_prop,
                 const int* __restrict__ slates, int n_slates,
                 float* __restrict__ out) {
    extern __shared__ __align__(16) float sm[];
    float*  x1s  = sm + OFF_X1;                       // [50][132]
    float*  psum = sm + OFF_PSUM;                     // [2][50][33]
    float*  upss = sm + OFF_UPS;                      // [8][128]
    float*  ues  = sm + OFF_UE;                       // [8][64]
    float*  t1s  = sm + OFF_T1;                       // [8][32]
    float*  hbuf = sm + OFF_HB;                       // [8][32]
    float2* pcs  = (float2*)(sm + OFF_PCS);           // [8][52] (ps, ss)
    float*  qws  = sm + OFF_QW;                       // [32]
    float*  n2bs = sm + OFF_N2B;                      // [32]

    const int tid = threadIdx.x;
    const int wid = tid >> 5;
    const int lane = tid & 31;
    const int u0 = blockIdx.x * UB;

    if (tid < 32) qws[tid] = q_W[tid];
    else if (tid < 64) n2bs[tid - 32] = n2_b[tid - 32];

    // ================= Phase A: LSTM, warp = user =================
    {
        const int u = u0 + wid;
        float wh[LU][4];
#pragma unroll
        for (int k = 0; k < LU; k++)
#pragma unroll
            for (int g = 0; g < 4; g++)
                wh[k][g] = lstm_Wh[k * ZDIM + g * 32 + lane];
        float wlast[4];
#pragma unroll
        for (int g = 0; g < 4; g++)
            wlast[g] = lstm_Wx[DD * ZDIM + g * 32 + lane];

        const int* ids = doc_ids + u * TT;
        const float* cts = ctime + u * TT;
        int id = __ldg(&ids[0]);
        float ctn = __ldg(&cts[0]);

        hbuf[wid * LU + lane] = 0.0f;
        __syncwarp();

        float h = 0.0f, c = 0.0f;
#pragma unroll 1
        for (int t = 0; t < TT; t++) {
            const float4 pf = *(const float4*)(g_P + id * ZDIM + lane * 4);
            float ct = ctn;
            if (t + 1 < TT) { id = __ldg(&ids[t + 1]); ctn = __ldg(&cts[t + 1]); }
            float z0 = fmaf(ct, wlast[0], pf.x);
            float z1 = fmaf(ct, wlast[1], pf.y);
            float z2 = fmaf(ct, wlast[2], pf.z);
            float z3 = fmaf(ct, wlast[3], pf.w);
            const float4* hb4 = (const float4*)(hbuf + wid * LU);
#pragma unroll
            for (int kq = 0; kq < LU / 4; kq++) {
                float4 hq = hb4[kq];
                int k = kq * 4;
                z0 = fmaf(hq.x, wh[k][0], z0); z1 = fmaf(hq.x, wh[k][1], z1);
                z2 = fmaf(hq.x, wh[k][2], z2); z3 = fmaf(hq.x, wh[k][3], z3);
                z0 = fmaf(hq.y, wh[k+1][0], z0); z1 = fmaf(hq.y, wh[k+1][1], z1);
                z2 = fmaf(hq.y, wh[k+1][2], z2); z3 = fmaf(hq.y, wh[k+1][3], z3);
                z0 = fmaf(hq.z, wh[k+2][0], z0); z1 = fmaf(hq.z, wh[k+2][1], z1);
                z2 = fmaf(hq.z, wh[k+2][2], z2); z3 = fmaf(hq.z, wh[k+2][3], z3);
                z0 = fmaf(hq.w, wh[k+3][0], z0); z1 = fmaf(hq.w, wh[k+3][1], z1);
                z2 = fmaf(hq.w, wh[k+3][2], z2); z3 = fmaf(hq.w, wh[k+3][3], z3);
            }
            float gi = sigf(z0), gf = sigf(z1), gg = tanhfast(z2), go = sigf(z3);
            c = fmaf(gf, c, gi * gg);
            h = go * tanhfast(c);
            __syncwarp();
            hbuf[wid * LU + lane] = h;
            __syncwarp();
        }
    }
    __syncthreads();   // h for all 8 users visible

    // ================= Phase B: head matvecs, batched over 8 users =================
    // t1 = lrelu(h @ d1_W + b) : 256 = 8*32 exact
    {
        int uu = tid >> 5, i = tid & 31;
        float acc = d1_b[i];
        const float* hrow = hbuf + uu * LU;
#pragma unroll
        for (int k = 0; k < LU; k++) acc = fmaf(hrow[k], d1_W[k * LU + i], acc);
        t1s[uu * LU + i] = acc >= 0.0f ? acc : 0.3f * acc;
    }
    __syncthreads();
    // ue = t1 @ he_W + b : 8*64 = 512 = 2 iters
#pragma unroll
    for (int it = 0; it < 2; it++) {
        int idx = tid + it * 256;
        int uu = idx >> 6, i = idx & 63;
        float acc = he_b[i];
        const float* trow = t1s + uu * LU;
#pragma unroll
        for (int k = 0; k < LU; k++) acc = fmaf(trow[k], he_W[k * DD + i], acc);
        ues[uu * DD + i] = acc;
    }
    __syncthreads();
    // ups = ue @ n1_W[0:64] : 8*128 = 1024 = 4 iters
#pragma unroll
    for (int it = 0; it < 4; it++) {
        int idx = tid + it * 256;
        int uu = idx >> 7, col = idx & 127;
        const float* uerow = ues + uu * DD;
        float acc = 0.0f;
#pragma unroll 8
        for (int k = 0; k < DD; k++) acc = fmaf(uerow[k], n1_W[k * ZDIM + col], acc);
        upss[uu * ZDIM + col] = acc;
    }
    // ss = exp(ue . doc_feat) : 8*50 = 400
#pragma unroll
    for (int it = 0; it < 2; it++) {
        int idx = tid + it * 256;
        if (idx < UB * NDOCS) {
            int uu = idx / NDOCS, d = idx - uu * NDOCS;
            const float* uerow = ues + uu * DD;
            const float* df = doc_prop + (d + 1) * DD;
            float acc = 0.0f;
#pragma unroll 8
            for (int k = 0; k < DD; k++) acc = fmaf(uerow[k], __ldg(&df[k]), acc);
            pcs[uu * 52 + d].y = __expf(acc);
        }
    }

    // ---- B column slice into registers (uniform per warp kh) ----
    const int kh = wid & 1;
    const int dg = wid >> 1;    // 0..3
    u64 breg[32];
    {
        const float* wp = n2_W + (kh * 64) * 32 + lane;
#pragma unroll
        for (int j = 0; j < 32; j++)
            breg[j] = pack2(wp[(2 * j) * 32], wp[(2 * j + 1) * 32]);
    }
    __syncthreads();

    // ================= Phase C: per-user x1 -> GEMM -> ps =================
#pragma unroll 1
    for (int j = 0; j < UB; j++) {
        // x1[d][k] = relu(ups[j][k] + dpart[d][k])
        {
            const float4* dp4 = (const float4*)g_dpart;
            const float4* up4 = (const float4*)(upss + j * ZDIM);
            for (int i = tid; i < NDOCS * (ZDIM / 4); i += 256) {
                int d = i >> 5, kq = i & 31;
                float4 v = dp4[i];
                float4 uu = up4[kq];
                v.x = fmaxf(v.x + uu.x, 0.0f);
                v.y = fmaxf(v.y + uu.y, 0.0f);
                v.z = fmaxf(v.z + uu.z, 0.0f);
                v.w = fmaxf(v.w + uu.w, 0.0f);
                *(float4*)(x1s + d * X1S + kq * 4) = v;
            }
        }
        __syncthreads();

        // GEMM: warp = (dg, kh); lane = column
        {
            const int nd = (dg == 3) ? 11 : 13;
#pragma unroll 1
            for (int dd = 0; dd < nd; dd++) {
                const int d = dg * 13 + dd;
                const ulonglong2* ap = (const ulonglong2*)(x1s + d * X1S + kh * 64);
                u64 acc = 0ull;
#pragma unroll
                for (int q = 0; q < 16; q++) {
                    ulonglong2 av = ap[q];
                    acc = ffma2(av.x, breg[2 * q], acc);
                    acc = ffma2(av.y, breg[2 * q + 1], acc);
                }
                float lo, hi;
                unpack2(acc, lo, hi);
                psum[(kh * NDOCS + d) * 33 + lane] = lo + hi;
            }
        }
        __syncthreads();

        // epilogue: ps = ss * (relu(psum0+psum1+b).qw + qb)
        if (tid < NDOCS) {
            float qs = 0.0f;
#pragma unroll
            for (int c = 0; c < 32; c++) {
                float x2 = psum[tid * 33 + c] + psum[(NDOCS + tid) * 33 + c] + n2bs[c];
                qs = fmaf(fmaxf(x2, 0.0f), qws[c], qs);
            }
            pcs[j * 52 + tid].x = pcs[j * 52 + tid].y * (qs + q_b[0]);
        }
        __syncthreads();
    }

    // ================= Phase D: slate aggregation, 8 users per slate read =================
    const int2* sl2 = (const int2*)slates;
    for (int si = tid; si < n_slates; si += 256) {
        int2 pr = __ldg(&sl2[si]);
#pragma unroll
        for (int uu = 0; uu < UB; uu++) {
            float2 a = pcs[uu * 52 + pr.x];
            float2 b = pcs[uu * 52 + pr.y];
            float num = a.x + b.x;
            float den = a.y + b.y + 1.0f;
            __stcs(&out[(size_t)(u0 + uu) * (size_t)n_slates + si], __fdividef(num, den));
        }
    }
}

extern "C" void kernel_launch(void* const* d_in, const int* in_sizes, int n_in,
                              void* d_out, int out_size) {
    const int*   doc_ids   = (const int*)d_in[0];
    const float* ctime     = (const float*)d_in[1];
    const int*   slates    = (const int*)d_in[2];
    const float* doc_embed = (const float*)d_in[3];
    const float* doc_prop  = (const float*)d_in[4];
    const float* Wx        = (const float*)d_in[5];
    const float* Wh        = (const float*)d_in[6];
    const float* lb        = (const float*)d_in[7];
    const float* d1W       = (const float*)d_in[8];
    const float* d1b       = (const float*)d_in[9];
    const float* heW       = (const float*)d_in[10];
    const float* heb       = (const float*)d_in[11];
    const float* n1W       = (const float*)d_in[12];
    const float* n1b       = (const float*)d_in[13];
    const float* n2W       = (const float*)d_in[14];
    const float* n2b       = (const float*)d_in[15];
    const float* qW        = (const float*)d_in[16];
    const float* qb        = (const float*)d_in[17];
    const int n_slates = in_sizes[2] / 2;

    cudaFuncSetAttribute(mega_kernel, cudaFuncAttributeMaxDynamicSharedMemorySize, SMEM_BYTES);

    precompute_kernel<<<2 * NDOCS + 1, ZDIM>>>(doc_embed, Wx, lb, doc_prop, n1W, n1b);
    mega_kernel<<<NUSERS / UB, 256, SMEM_BYTES>>>(doc_ids, ctime, Wh, Wx,
                                                  d1W, d1b, heW, heb, n1W, n2W, n2b, qW, qb,
                                                  doc_prop, slates, n_slates, (float*)d_out);
}

// round 15
// speedup vs baseline: 1.4145x; 1.4145x over previous
#include <cuda_runtime.h>
#include <cstdint>

#define TT 50
#define NUSERS 4096
#define NDOCS 50
#define DD 64
#define LU 32
#define ZDIM 128
#define X1STRIDE 132

typedef unsigned long long u64;

__device__ __forceinline__ u64 pack2(float lo, float hi) {
    u64 r; asm("mov.b64 %0, {%1, %2};" : "=l"(r) : "f"(lo), "f"(hi)); return r;
}
__device__ __forceinline__ u64 dup2(float x) { return pack2(x, x); }
__device__ __forceinline__ void unpack2(u64 v, float& lo, float& hi) {
    asm("mov.b64 {%0, %1}, %2;" : "=f"(lo), "=f"(hi) : "l"(v));
}
__device__ __forceinline__ u64 ffma2(u64 a, u64 b, u64 c) {
    u64 d; asm("fma.rn.f32x2 %0, %1, %2, %3;" : "=l"(d) : "l"(a), "l"(b), "l"(c)); return d;
}

// -------- device scratch --------
__device__ __align__(16) float g_P[(NDOCS + 1) * ZDIM];   // [id][lane][gate] -> pair-ready
__device__ __align__(16) float g_dpart[NDOCS * ZDIM];
__device__ __align__(16) float g_dpT[DD * 64];            // transposed doc_prop [k][d], stride 64
__device__ float g_h[NUSERS * LU];

__device__ __forceinline__ float sigf(float x) { return 1.0f / (1.0f + __expf(-x)); }
__device__ __forceinline__ float tanhfast(float x) { return 2.0f / (1.0f + __expf(-2.0f * x)) - 1.0f; }

// ---------------- K0: precompute P, dpart, doc_prop^T ----------------
__global__ void precompute_kernel(const float* __restrict__ doc_embed,
                                  const float* __restrict__ lstm_Wx,
                                  const float* __restrict__ lstm_b,
                                  const float* __restrict__ doc_prop,
                                  const float* __restrict__ n1_W,
                                  const float* __restrict__ n1_b) {
    int c = threadIdx.x;
    int b = blockIdx.x;
    if (b <= NDOCS) {
        int lane = c >> 2, g = c & 3;
        int col = g * 32 + lane;
        float acc = lstm_b[col];
#pragma unroll 8
        for (int k = 0; k < DD; k++)
            acc = fmaf(doc_embed[b * DD + k], lstm_Wx[k * ZDIM + col], acc);
        g_P[b * ZDIM + c] = acc;
    } else if (b <= 2 * NDOCS) {
        int d = b - (NDOCS + 1);
        float acc = n1_b[c];
#pragma unroll 8
        for (int k = 0; k < DD; k++)
            acc = fmaf(doc_prop[(d + 1) * DD + k], n1_W[(DD + k) * ZDIM + c], acc);
        g_dpart[d * ZDIM + c] = acc;
    } else {
        // transpose doc_prop[1..50] -> g_dpT[k][d]
        for (int idx = c; idx < DD * 64; idx += ZDIM) {
            int k = idx >> 6, d = idx & 63;
            g_dpT[idx] = (d < NDOCS) ? doc_prop[(d + 1) * DD + k] : 0.0f;
        }
    }
}

// ---------------- K1: LSTM — dup-h smem pairs + FFMA2, zero packing movs ----------------
__global__ __launch_bounds__(128, 3)
void lstm_kernel(const int* __restrict__ doc_ids,
                 const float* __restrict__ ctime,
                 const float* __restrict__ lstm_Wh,
                 const float* __restrict__ lstm_Wx) {
    __shared__ __align__(16) float hd[4][2 * LU];   // duplicated h: hd[2i]=hd[2i+1]=h_i
    const int lane = threadIdx.x & 31;
    const int w = threadIdx.x >> 5;
    const int u = blockIdx.x * 4 + w;

    // packed Wh columns: whp0[k]=(gates 0,1), whp1[k]=(gates 2,3) for this lane
    u64 whp0[LU], whp1[LU];
#pragma unroll
    for (int k = 0; k < LU; k++) {
        whp0[k] = pack2(lstm_Wh[k * ZDIM + lane],      lstm_Wh[k * ZDIM + 32 + lane]);
        whp1[k] = pack2(lstm_Wh[k * ZDIM + 64 + lane], lstm_Wh[k * ZDIM + 96 + lane]);
    }
    const u64 wl01 = pack2(lstm_Wx[DD * ZDIM + lane],      lstm_Wx[DD * ZDIM + 32 + lane]);
    const u64 wl23 = pack2(lstm_Wx[DD * ZDIM + 64 + lane], lstm_Wx[DD * ZDIM + 96 + lane]);

    const int* ids = doc_ids + u * TT;
    const float* cts = ctime + u * TT;
    int id = __ldg(&ids[0]);
    float ctn = __ldg(&cts[0]);

    *(u64*)&hd[w][2 * lane] = 0ull;
    __syncwarp();

    float h = 0.0f, c = 0.0f;
#pragma unroll 1
    for (int t = 0; t < TT; t++) {
        // g_P row: (g0,g1),(g2,g3) pairs direct from one LDG.128
        const ulonglong2 pp = *(const ulonglong2*)(g_P + id * ZDIM + lane * 4);
        float ct = ctn;
        if (t + 1 < TT) { id = __ldg(&ids[t + 1]); ctn = __ldg(&cts[t + 1]); }
        u64 ctd = dup2(ct);
        u64 z01 = ffma2(ctd, wl01, pp.x);
        u64 z23 = ffma2(ctd, wl23, pp.y);
        const ulonglong2* hb = (const ulonglong2*)hd[w];
#pragma unroll
        for (int q = 0; q < LU / 2; q++) {
            ulonglong2 hv = hb[q];          // (h_2q,h_2q) , (h_2q+1,h_2q+1)
            z01 = ffma2(hv.x, whp0[2 * q], z01);
            z23 = ffma2(hv.x, whp1[2 * q], z23);
            z01 = ffma2(hv.y, whp0[2 * q + 1], z01);
            z23 = ffma2(hv.y, whp1[2 * q + 1], z23);
        }
        float za, zb, zc, zd;
        unpack2(z01, za, zb);
        unpack2(z23, zc, zd);
        float gi = sigf(za), gf = sigf(zb), gg = tanhfast(zc), go = sigf(zd);
        c = fmaf(gf, c, gi * gg);
        h = go * tanhfast(c);
        __syncwarp();
        *(u64*)&hd[w][2 * lane] = dup2(h);
        __syncwarp();
    }
    g_h[u * LU + lane] = h;
}

// ---------------- K2: per-user head + Q-net + slate (R7 + coalesced ss) ----------------
__global__ __launch_bounds__(256)
void user_kernel(const float* __restrict__ d1_W, const float* __restrict__ d1_b,
                 const float* __restrict__ he_W, const float* __restrict__ he_b,
                 const float* __restrict__ n1_W,
                 const float* __restrict__ n2_W, const float* __restrict__ n2_b,
                 const float* __restrict__ q_W, const float* __restrict__ q_b,
                 const int* __restrict__ slates, int n_slates,
                 float* __restrict__ out) {
    __shared__ __align__(16) float x1s[NDOCS * X1STRIDE];
    __shared__ __align__(16) float w2s[ZDIM * 32];
    __shared__ __align__(16) float ups[ZDIM];
    __shared__ float qpart[NDOCS * 8];
    __shared__ float ue[DD];
    __shared__ float t1[LU];
    __shared__ float hs[LU];
    __shared__ float ss[NDOCS];
    __shared__ float ps[NDOCS];
    __shared__ float qss[NDOCS];
    __shared__ float qw[32];
    __shared__ float n2bs[32];

    const int tid = threadIdx.x;
    const int u = blockIdx.x;

    if (tid < LU) hs[tid] = g_h[u * LU + tid];
    if (tid >= 32 && tid < 64) qw[tid - 32] = q_W[tid - 32];
    if (tid >= 64 && tid < 96) n2bs[tid - 64] = n2_b[tid - 64];
    {
        const float4* src = (const float4*)n2_W;
        float4* dst = (float4*)w2s;
        for (int i = tid; i < ZDIM * 32 / 4; i += 256) dst[i] = src[i];
    }
    __syncthreads();

    if (tid < LU) {
        float acc = d1_b[tid];
#pragma unroll
        for (int k = 0; k < LU; k++) acc = fmaf(hs[k], d1_W[k * LU + tid], acc);
        t1[tid] = acc >= 0.0f ? acc : 0.3f * acc;
    }
    __syncthreads();

    if (tid < DD) {
        float acc = he_b[tid];
#pragma unroll
        for (int k = 0; k < LU; k++) acc = fmaf(t1[k], he_W[k * DD + tid], acc);
        ue[tid] = acc;
    }
    __syncthreads();

    if (tid < ZDIM) {
        float acc = 0.0f;
#pragma unroll 8
        for (int k = 0; k < DD; k++) acc = fmaf(ue[k], n1_W[k * ZDIM + tid], acc);
        ups[tid] = acc;
    } else if (tid < ZDIM + NDOCS) {
        // coalesced: lane = doc, stride-64 transposed table
        int d = tid - ZDIM;
        float acc = 0.0f;
#pragma unroll 8
        for (int k = 0; k < DD; k++) acc = fmaf(ue[k], __ldg(&g_dpT[k * 64 + d]), acc);
        ss[d] = __expf(acc);
    }
    __syncthreads();

    {
        const float4* dp4 = (const float4*)g_dpart;
        const float4* up4 = (const float4*)ups;
        float4* x14 = (float4*)x1s;
        for (int i = tid; i < NDOCS * (ZDIM / 4); i += 256) {
            int d = i >> 5, kq = i & 31;
            float4 v = dp4[i];
            float4 uu = up4[kq];
            v.x = fmaxf(v.x + uu.x, 0.0f);
            v.y = fmaxf(v.y + uu.y, 0.0f);
            v.z = fmaxf(v.z + uu.z, 0.0f);
            v.w = fmaxf(v.w + uu.w, 0.0f);
            x14[d * (X1STRIDE / 4) + kq] = v;
        }
    }
    __syncthreads();

    if (tid < 200) {
        const int tx = tid & 7;
        const int ty = tid >> 3;
        const int d0 = ty, d1 = ty + 25;
        const float4* a0 = (const float4*)(x1s + d0 * X1STRIDE);
        const float4* a1 = (const float4*)(x1s + d1 * X1STRIDE);
        const ulonglong2* w2v = (const ulonglong2*)w2s;
        u64 acc00 = 0ull, acc01v = 0ull;
        u64 acc10 = 0ull, acc11v = 0ull;
#pragma unroll 8
        for (int kq = 0; kq < ZDIM / 4; kq++) {
            float4 va0 = a0[kq];
            float4 va1 = a1[kq];
            ulonglong2 b0 = w2v[(4 * kq + 0) * 8 + tx];
            ulonglong2 b1 = w2v[(4 * kq + 1) * 8 + tx];
            ulonglong2 b2 = w2v[(4 * kq + 2) * 8 + tx];
            ulonglong2 b3 = w2v[(4 * kq + 3) * 8 + tx];
            u64 a;
            a = dup2(va0.x); acc00 = ffma2(a, b0.x, acc00); acc01v = ffma2(a, b0.y, acc01v);
            a = dup2(va1.x); acc10 = ffma2(a, b0.x, acc10); acc11v = ffma2(a, b0.y, acc11v);
            a = dup2(va0.y); acc00 = ffma2(a, b1.x, acc00); acc01v = ffma2(a, b1.y, acc01v);
            a = dup2(va1.y); acc10 = ffma2(a, b1.x, acc10); acc11v = ffma2(a, b1.y, acc11v);
            a = dup2(va0.z); acc00 = ffma2(a, b2.x, acc00); acc01v = ffma2(a, b2.y, acc01v);
            a = dup2(va1.z); acc10 = ffma2(a, b2.x, acc10); acc11v = ffma2(a, b2.y, acc11v);
            a = dup2(va0.w); acc00 = ffma2(a, b3.x, acc00); acc01v = ffma2(a, b3.y, acc01v);
            a = dup2(va1.w); acc10 = ffma2(a, b3.x, acc10); acc11v = ffma2(a, b3.y, acc11v);
        }
        const int c0 = tx * 4;
        float s0, s1, s2, s3;
        unpack2(acc00, s0, s1); unpack2(acc01v, s2, s3);
        float qp0 = fmaxf(s0 + n2bs[c0 + 0], 0.f) * qw[c0 + 0];
        qp0 = fmaf(fmaxf(s1 + n2bs[c0 + 1], 0.f), qw[c0 + 1], qp0);
        qp0 = fmaf(fmaxf(s2 + n2bs[c0 + 2], 0.f), qw[c0 + 2], qp0);
        qp0 = fmaf(fmaxf(s3 + n2bs[c0 + 3], 0.f), qw[c0 + 3], qp0);
        float qp1 = fmaxf(s0 * 0.0f, 0.f);  // placeholder overwritten below
        unpack2(acc10, s0, s1); unpack2(acc11v, s2, s3);
        qp1 = fmaxf(s0 + n2bs[c0 + 0], 0.f) * qw[c0 + 0];
        qp1 = fmaf(fmaxf(s1 + n2bs[c0 + 1], 0.f), qw[c0 + 1], qp1);
        qp1 = fmaf(fmaxf(s2 + n2bs[c0 + 2], 0.f), qw[c0 + 2], qp1);
        qp1 = fmaf(fmaxf(s3 + n2bs[c0 + 3], 0.f), qw[c0 + 3], qp1);
        qpart[d0 * 8 + tx] = qp0;
        qpart[d1 * 8 + tx] = qp1;
    }
    __syncthreads();

    if (tid < NDOCS) {
        const float* qp = qpart + tid * 8;
        float q = ((qp[0] + qp[1]) + (qp[2] + qp[3])) + ((qp[4] + qp[5]) + (qp[6] + qp[7]));
        qss[tid] = q;
    }
    __syncthreads();

    if (tid < NDOCS) ps[tid] = ss[tid] * (qss[tid] + q_b[0]);
    __syncthreads();

    float* orow = out + (size_t)u * (size_t)n_slates;
    const int2* sl2 = (const int2*)slates;
    for (int si = tid; si < n_slates; si += 256) {
        int2 pr = __ldg(&sl2[si]);
        float num = ps[pr.x] + ps[pr.y];
        float den = ss[pr.x] + ss[pr.y] + 1.0f;
        __stcs(&orow[si], __fdividef(num, den));
    }
}

extern "C" void kernel_launch(void* const* d_in, const int* in_sizes, int n_in,
                              void* d_out, int out_size) {
    const int*   doc_ids   = (const int*)d_in[0];
    const float* ctime     = (const float*)d_in[1];
    const int*   slates    = (const int*)d_in[2];
    const float* doc_embed = (const float*)d_in[3];
    const float* doc_prop  = (const float*)d_in[4];
    const float* Wx        = (const float*)d_in[5];
    const float* Wh        = (const float*)d_in[6];
    const float* lb        = (const float*)d_in[7];
    const float* d1W       = (const float*)d_in[8];
    const float* d1b       = (const float*)d_in[9];
    const float* heW       = (const float*)d_in[10];
    const float* heb       = (const float*)d_in[11];
    const float* n1W       = (const float*)d_in[12];
    const float* n1b       = (const float*)d_in[13];
    const float* n2W       = (const float*)d_in[14];
    const float* n2b       = (const float*)d_in[15];
    const float* qW        = (const float*)d_in[16];
    const float* qb        = (const float*)d_in[17];
    const int n_slates = in_sizes[2] / 2;

    precompute_kernel<<<2 * NDOCS + 2, ZDIM>>>(doc_embed, Wx, lb, doc_prop, n1W, n1b);
    lstm_kernel<<<NUSERS / 4, 128>>>(doc_ids, ctime, Wh, Wx);
    user_kernel<<<NUSERS, 256>>>(d1W, d1b, heW, heb, n1W, n2W, n2b, qW, qb,
                                 slates, n_slates, (float*)d_out);
}